// round 4
// baseline (speedup 1.0000x reference)
#include <cuda_runtime.h>
#include <cuda_bf16.h>

#define N_NODES 100000
#define N_EDGES 1600000
#define DFEAT   128
#define NSCAN_BLOCKS 98   // ceil(100000 / 1024)

typedef unsigned long long u64;
typedef unsigned int u32;

// ---------------- scratch (static __device__, no allocs) ----------------
__device__ __align__(16) float g_h[N_NODES * DFEAT];     // post-GEMM features (pre-scaled by dinv)
__device__ __align__(16) float g_agg[N_NODES * DFEAT];   // post-aggregate (layer1 out)
__device__ float g_dinv[N_NODES];
__device__ int   g_cnt[N_NODES];
__device__ int   g_fill[N_NODES];
__device__ int   g_rowptr[N_NODES + 1];
__device__ int   g_blocksums[256];
__device__ int   g_col[N_EDGES];
// split-bf16 weights (row j contiguous in k)
__device__ __align__(16) __nv_bfloat16 g_w1hi[16384], g_w1lo[16384];
__device__ __align__(16) __nv_bfloat16 g_w2hi[16384], g_w2lo[16384];

// ---------------- CSR build kernels ----------------
__global__ void k_zero() {
    int i = blockIdx.x * 256 + threadIdx.x;
    if (i < N_NODES) { g_cnt[i] = 0; g_fill[i] = 0; }
}

__global__ void k_hist(const int* __restrict__ dst) {
    int e = blockIdx.x * 256 + threadIdx.x;
    if (e < N_EDGES) atomicAdd(&g_cnt[dst[e]], 1);
}

__global__ void k_dinv() {
    int i = blockIdx.x * 256 + threadIdx.x;
    if (i < N_NODES) g_dinv[i] = rsqrtf((float)(g_cnt[i] + 1));  // +1 self loop
}

__global__ void k_scan1() {
    __shared__ int sd[256];
    int tid = threadIdx.x;
    int base = blockIdx.x * 1024 + tid * 4;
    int s = 0;
    #pragma unroll
    for (int c = 0; c < 4; ++c)
        if (base + c < N_NODES) s += g_cnt[base + c];
    sd[tid] = s;
    __syncthreads();
    #pragma unroll
    for (int off = 128; off > 0; off >>= 1) {
        if (tid < off) sd[tid] += sd[tid + off];
        __syncthreads();
    }
    if (tid == 0) g_blocksums[blockIdx.x] = sd[0];
}

__global__ void k_scan2() {
    __shared__ int sh[128];
    int tid = threadIdx.x;
    sh[tid] = (tid < NSCAN_BLOCKS) ? g_blocksums[tid] : 0;
    __syncthreads();
    #pragma unroll
    for (int off = 1; off < 128; off <<= 1) {
        int t = (tid >= off) ? sh[tid - off] : 0;
        __syncthreads();
        sh[tid] += t;
        __syncthreads();
    }
    int excl = (tid == 0) ? 0 : sh[tid - 1];
    if (tid < NSCAN_BLOCKS) g_blocksums[tid] = excl;
    if (tid == 0) g_rowptr[N_NODES] = N_EDGES;
}

__global__ void k_scan3() {
    __shared__ int sh[256];
    int tid = threadIdx.x;
    int base = blockIdx.x * 1024 + tid * 4;
    int c0 = 0, c1 = 0, c2 = 0, c3 = 0;
    if (base + 0 < N_NODES) c0 = g_cnt[base + 0];
    if (base + 1 < N_NODES) c1 = g_cnt[base + 1];
    if (base + 2 < N_NODES) c2 = g_cnt[base + 2];
    if (base + 3 < N_NODES) c3 = g_cnt[base + 3];
    sh[tid] = c0 + c1 + c2 + c3;
    __syncthreads();
    #pragma unroll
    for (int off = 1; off < 256; off <<= 1) {
        int t = (tid >= off) ? sh[tid - off] : 0;
        __syncthreads();
        sh[tid] += t;
        __syncthreads();
    }
    int excl = (tid == 0) ? 0 : sh[tid - 1];
    int e = g_blocksums[blockIdx.x] + excl;
    if (base + 0 < N_NODES) g_rowptr[base + 0] = e;
    if (base + 1 < N_NODES) g_rowptr[base + 1] = e + c0;
    if (base + 2 < N_NODES) g_rowptr[base + 2] = e + c0 + c1;
    if (base + 3 < N_NODES) g_rowptr[base + 3] = e + c0 + c1 + c2;
}

__global__ void k_fill(const int* __restrict__ src, const int* __restrict__ dst) {
    int e = blockIdx.x * 256 + threadIdx.x;
    if (e < N_EDGES) {
        int d = dst[e];
        int p = g_rowptr[d] + atomicAdd(&g_fill[d], 1);
        g_col[p] = src[e];
    }
}

// ---------------- weight split: W -> (hi, lo) bf16 ----------------
__global__ void k_prep(const float* __restrict__ W1, const float* __restrict__ W2) {
    int i = blockIdx.x * 256 + threadIdx.x;
    if (i < 16384) {
        float v = W1[i];
        __nv_bfloat16 h = __float2bfloat16(v);
        g_w1hi[i] = h;
        g_w1lo[i] = __float2bfloat16(v - __bfloat162float(h));
        v = W2[i];
        h = __float2bfloat16(v);
        g_w2hi[i] = h;
        g_w2lo[i] = __float2bfloat16(v - __bfloat162float(h));
    }
}

// ---------------- mma.sync helpers ----------------
__device__ __forceinline__ void mma16816(float* c, const u32* a, const u32* b) {
    asm volatile(
        "mma.sync.aligned.m16n8k16.row.col.f32.bf16.bf16.f32 "
        "{%0,%1,%2,%3}, {%4,%5,%6,%7}, {%8,%9}, {%0,%1,%2,%3};"
        : "+f"(c[0]), "+f"(c[1]), "+f"(c[2]), "+f"(c[3])
        : "r"(a[0]), "r"(a[1]), "r"(a[2]), "r"(a[3]), "r"(b[0]), "r"(b[1]));
}

// ---------------- tensor-core GEMM (mma.sync, split-bf16 3-product) ----------------
// g_h[i][j] = dinv[i] * sum_k A[i][k] * W[j][k]
// CTA tile 128x128, K=128 in 8 chunks of 16. 8 warps = 2(m) x 4(n); warp tile 64x32.
// SMEM tiles: pitch 136 bf16 (272 B) -> conflict-free fragment LDS.
#define TPITCH 272            // bytes per tile row (136 bf16)
#define TILE_B (128 * TPITCH) // 34816
#define OFF_AHI 0
#define OFF_ALO TILE_B
#define OFF_BHI (2 * TILE_B)
#define OFF_BLO (3 * TILE_B)
#define GEMM_SMEM (4 * TILE_B)   // 139264
#define SPITCH 136            // stage pitch (floats)

template <int PHASE>
__global__ __launch_bounds__(256, 1)
void k_mgemm(const float* __restrict__ Aext) {
    extern __shared__ char smem[];
    const float* __restrict__ A = (PHASE == 0) ? Aext : g_agg;
    const u64* __restrict__ whi = reinterpret_cast<const u64*>((PHASE == 0) ? g_w1hi : g_w2hi);
    const u64* __restrict__ wlo = reinterpret_cast<const u64*>((PHASE == 0) ? g_w1lo : g_w2lo);

    const int tid = threadIdx.x;
    const int wid = tid >> 5;
    const int lane = tid & 31;
    const int g = lane >> 2;     // group id (0..7)
    const int tg = lane & 3;     // thread in group
    const int wm = wid >> 2;     // 0..1  (m: 64 rows)
    const int wn = wid & 3;      // 0..3  (n: 32 cols)
    const int rowBase = blockIdx.x * 128;

    // --- load A tile (fp32), split hi/lo bf16, store to SMEM padded ---
    const float4* __restrict__ A4 = reinterpret_cast<const float4*>(A);
    for (int idx = tid; idx < 4096; idx += 256) {
        int row = idx >> 5;          // 0..127
        int c4 = idx & 31;           // float4 column group
        int grow = rowBase + row;
        float4 v = make_float4(0.f, 0.f, 0.f, 0.f);
        if (grow < N_NODES) v = A4[grow * 32 + c4];
        __nv_bfloat16 h0 = __float2bfloat16(v.x), h1 = __float2bfloat16(v.y);
        __nv_bfloat16 h2 = __float2bfloat16(v.z), h3 = __float2bfloat16(v.w);
        __nv_bfloat16 l0 = __float2bfloat16(v.x - __bfloat162float(h0));
        __nv_bfloat16 l1 = __float2bfloat16(v.y - __bfloat162float(h1));
        __nv_bfloat16 l2 = __float2bfloat16(v.z - __bfloat162float(h2));
        __nv_bfloat16 l3 = __float2bfloat16(v.w - __bfloat162float(h3));
        u64 hv = (u64)__bfloat16_as_ushort(h0) | ((u64)__bfloat16_as_ushort(h1) << 16) |
                 ((u64)__bfloat16_as_ushort(h2) << 32) | ((u64)__bfloat16_as_ushort(h3) << 48);
        u64 lv = (u64)__bfloat16_as_ushort(l0) | ((u64)__bfloat16_as_ushort(l1) << 16) |
                 ((u64)__bfloat16_as_ushort(l2) << 32) | ((u64)__bfloat16_as_ushort(l3) << 48);
        int off = row * TPITCH + c4 * 8;
        *reinterpret_cast<u64*>(smem + OFF_AHI + off) = hv;
        *reinterpret_cast<u64*>(smem + OFF_ALO + off) = lv;
    }
    // --- load B tiles (pre-split bf16 weights) ---
    for (int idx = tid; idx < 4096; idx += 256) {
        int row = idx >> 5;
        int c4 = idx & 31;
        int off = row * TPITCH + c4 * 8;
        *reinterpret_cast<u64*>(smem + OFF_BHI + off) = whi[idx];
        *reinterpret_cast<u64*>(smem + OFF_BLO + off) = wlo[idx];
    }
    __syncthreads();

    float c[4][4][4];
    #pragma unroll
    for (int mi = 0; mi < 4; ++mi)
        #pragma unroll
        for (int ni = 0; ni < 4; ++ni)
            #pragma unroll
            for (int r = 0; r < 4; ++r) c[mi][ni][r] = 0.f;

    // per-thread base byte offsets inside tiles
    const int aBase = (wm * 64 + g) * TPITCH + tg * 4;   // A: row = wm*64 + mi*16 + g, k = tg*2
    const int bBase = (wn * 32 + g) * TPITCH + tg * 4;   // B: row(n) = wn*32 + ni*8 + g

    #pragma unroll
    for (int kc = 0; kc < 8; ++kc) {
        const int kb = kc * 32;  // 16 bf16 = 32 bytes
        u32 ah[4][4], al[4][4], bh[4][2], bl[4][2];
        #pragma unroll
        for (int mi = 0; mi < 4; ++mi) {
            int o = aBase + mi * (16 * TPITCH) + kb;
            ah[mi][0] = *reinterpret_cast<const u32*>(smem + OFF_AHI + o);
            ah[mi][1] = *reinterpret_cast<const u32*>(smem + OFF_AHI + o + 8 * TPITCH);
            ah[mi][2] = *reinterpret_cast<const u32*>(smem + OFF_AHI + o + 16);
            ah[mi][3] = *reinterpret_cast<const u32*>(smem + OFF_AHI + o + 8 * TPITCH + 16);
            al[mi][0] = *reinterpret_cast<const u32*>(smem + OFF_ALO + o);
            al[mi][1] = *reinterpret_cast<const u32*>(smem + OFF_ALO + o + 8 * TPITCH);
            al[mi][2] = *reinterpret_cast<const u32*>(smem + OFF_ALO + o + 16);
            al[mi][3] = *reinterpret_cast<const u32*>(smem + OFF_ALO + o + 8 * TPITCH + 16);
        }
        #pragma unroll
        for (int ni = 0; ni < 4; ++ni) {
            int o = bBase + ni * (8 * TPITCH) + kb;
            bh[ni][0] = *reinterpret_cast<const u32*>(smem + OFF_BHI + o);
            bh[ni][1] = *reinterpret_cast<const u32*>(smem + OFF_BHI + o + 16);
            bl[ni][0] = *reinterpret_cast<const u32*>(smem + OFF_BLO + o);
            bl[ni][1] = *reinterpret_cast<const u32*>(smem + OFF_BLO + o + 16);
        }
        #pragma unroll
        for (int mi = 0; mi < 4; ++mi)
            #pragma unroll
            for (int ni = 0; ni < 4; ++ni) {
                mma16816(c[mi][ni], ah[mi], bh[ni]);  // hi*hi
                mma16816(c[mi][ni], ah[mi], bl[ni]);  // hi*lo
                mma16816(c[mi][ni], al[mi], bh[ni]);  // lo*hi
            }
    }

    // --- epilogue: stage C to SMEM (overlay A tiles), scale by dinv, coalesced store ---
    __syncthreads();  // all warps done reading A tiles
    float* stage = reinterpret_cast<float*>(smem);   // 128 x SPITCH floats = 69632 B
    #pragma unroll
    for (int mi = 0; mi < 4; ++mi)
        #pragma unroll
        for (int ni = 0; ni < 4; ++ni) {
            int row0 = wm * 64 + mi * 16 + g;
            int col = wn * 32 + ni * 8 + tg * 2;
            stage[row0 * SPITCH + col]       = c[mi][ni][0];
            stage[row0 * SPITCH + col + 1]   = c[mi][ni][1];
            stage[(row0 + 8) * SPITCH + col]     = c[mi][ni][2];
            stage[(row0 + 8) * SPITCH + col + 1] = c[mi][ni][3];
        }
    __syncthreads();
    for (int i = tid; i < 4096; i += 256) {
        int row = i >> 5;
        int c4 = i & 31;
        int grow = rowBase + row;
        if (grow < N_NODES) {
            float sc = g_dinv[grow];
            float4 o;
            o.x = stage[row * SPITCH + c4 * 4 + 0] * sc;
            o.y = stage[row * SPITCH + c4 * 4 + 1] * sc;
            o.z = stage[row * SPITCH + c4 * 4 + 2] * sc;
            o.w = stage[row * SPITCH + c4 * 4 + 3] * sc;
            *reinterpret_cast<float4*>(&g_h[grow * 128 + c4 * 4]) = o;
        }
    }
}

// ---------------- Aggregate: out[d] = dinv[d]*(sum_{s in N(d)} hs[s] + hs[d]) + b + perturb
// hs = h pre-scaled by dinv (GEMM epilogue). One warp/node, float4/lane, CSR gather.
template <int PHASE>
__global__ __launch_bounds__(256)
void k_agg(const float* __restrict__ bias, const float* __restrict__ perturb,
           float* __restrict__ outParam) {
    int gw = (blockIdx.x * 256 + threadIdx.x) >> 5;
    if (gw >= N_NODES) return;
    const int lane = threadIdx.x & 31;
    const float4* __restrict__ hv = reinterpret_cast<const float4*>(g_h);
    float* __restrict__ outp = (PHASE == 0) ? g_agg : outParam;

    const int d = gw;
    const float dd = g_dinv[d];
    float4 v = hv[d * 32 + lane];              // self loop (already scaled by dinv[d])
    float ax = v.x, ay = v.y, az = v.z, aw = v.w;

    int j = g_rowptr[d];
    const int end = g_rowptr[d + 1];
    for (; j + 4 <= end; j += 4) {
        int s0 = g_col[j + 0], s1 = g_col[j + 1], s2 = g_col[j + 2], s3 = g_col[j + 3];
        float4 v0 = hv[s0 * 32 + lane];
        float4 v1 = hv[s1 * 32 + lane];
        float4 v2 = hv[s2 * 32 + lane];
        float4 v3 = hv[s3 * 32 + lane];
        ax += v0.x + v1.x + v2.x + v3.x;
        ay += v0.y + v1.y + v2.y + v3.y;
        az += v0.z + v1.z + v2.z + v3.z;
        aw += v0.w + v1.w + v2.w + v3.w;
    }
    for (; j < end; ++j) {
        int s = g_col[j];
        float4 vv = hv[s * 32 + lane];
        ax += vv.x; ay += vv.y; az += vv.z; aw += vv.w;
    }

    float4 b = reinterpret_cast<const float4*>(bias)[lane];
    float4 p = reinterpret_cast<const float4*>(perturb)[d * 32 + lane];
    float4 o;
    o.x = ax * dd + b.x + p.x;
    o.y = ay * dd + b.y + p.y;
    o.z = az * dd + b.z + p.z;
    o.w = aw * dd + b.w + p.w;
    reinterpret_cast<float4*>(outp)[d * 32 + lane] = o;
}

// ---------------- launch ----------------
extern "C" void kernel_launch(void* const* d_in, const int* in_sizes, int n_in,
                              void* d_out, int out_size) {
    const float* x  = (const float*)d_in[0];
    const int*   ei = (const int*)d_in[1];
    const float* pf = (const float*)d_in[2];
    const float* pl = (const float*)d_in[3];
    const float* W1 = (const float*)d_in[4];
    const float* b1 = (const float*)d_in[5];
    const float* W2 = (const float*)d_in[6];
    const float* b2 = (const float*)d_in[7];
    float* out = (float*)d_out;
    const int* src = ei;
    const int* dst = ei + N_EDGES;

    const int nb_nodes = (N_NODES + 255) / 256;       // 391
    const int nb_edges = (N_EDGES + 255) / 256;       // 6250
    const int nb_gemm  = (N_NODES + 127) / 128;       // 782
    const int nb_agg   = (N_NODES + 7) / 8;           // 12500

    cudaFuncSetAttribute(k_mgemm<0>, cudaFuncAttributeMaxDynamicSharedMemorySize, GEMM_SMEM);
    cudaFuncSetAttribute(k_mgemm<1>, cudaFuncAttributeMaxDynamicSharedMemorySize, GEMM_SMEM);

    // CSR + norm build (per call; deterministic work)
    k_zero<<<nb_nodes, 256>>>();
    k_hist<<<nb_edges, 256>>>(dst);
    k_dinv<<<nb_nodes, 256>>>();
    k_prep<<<64, 256>>>(W1, W2);
    k_scan1<<<NSCAN_BLOCKS, 256>>>();
    k_scan2<<<1, 128>>>();
    k_scan3<<<NSCAN_BLOCKS, 256>>>();
    k_fill<<<nb_edges, 256>>>(src, dst);

    // layer 1
    k_mgemm<0><<<nb_gemm, 256, GEMM_SMEM>>>(x);
    k_agg<0><<<nb_agg, 256>>>(b1, pf, nullptr);
    // layer 2
    k_mgemm<1><<<nb_gemm, 256, GEMM_SMEM>>>(nullptr);
    k_agg<1><<<nb_agg, 256>>>(b2, pl, out);
}

// round 6
// speedup vs baseline: 1.4595x; 1.4595x over previous
#include <cuda_runtime.h>
#include <cuda_bf16.h>
#include <cuda_fp16.h>

#define N_NODES 100000
#define N_EDGES 1600000
#define DFEAT   128
#define NSCAN_BLOCKS 98   // ceil(100000 / 1024)

typedef unsigned long long u64;
typedef unsigned int u32;

// ---------------- scratch (static __device__, no allocs) ----------------
__device__ __align__(16) __half g_hh[N_NODES * DFEAT];   // post-GEMM features, fp16, pre-scaled by dinv
__device__ __align__(16) float g_agg[N_NODES * DFEAT];   // post-aggregate (layer1 out, fp32)
__device__ float g_dinv[N_NODES];
__device__ int   g_cnt[N_NODES];
__device__ int   g_fill[N_NODES];
__device__ int   g_rowptr[N_NODES + 1];
__device__ int   g_blocksums[256];
__device__ int   g_col[N_EDGES];

// ---------------- f32x2 helpers (Blackwell packed fp32) ----------------
__device__ __forceinline__ u64 pack2dup(float a) {
    u64 r;
    asm("mov.b64 %0, {%1, %1};" : "=l"(r) : "f"(a));
    return r;
}
__device__ __forceinline__ void fma2(u64 &c, u64 a, u64 b) {
    asm("fma.rn.f32x2 %0, %1, %2, %0;" : "+l"(c) : "l"(a), "l"(b));
}
__device__ __forceinline__ float2 unpack2(u64 v) {
    float2 f;
    asm("mov.b64 {%0, %1}, %2;" : "=f"(f.x), "=f"(f.y) : "l"(v));
    return f;
}

// ---------------- CSR build kernels ----------------
__global__ void k_zero() {
    int i = blockIdx.x * 256 + threadIdx.x;
    if (i < N_NODES) g_cnt[i] = 0;
}

__global__ void k_hist(const int* __restrict__ dst) {
    int e = blockIdx.x * 256 + threadIdx.x;
    if (e < N_EDGES) atomicAdd(&g_cnt[dst[e]], 1);
}

__global__ void k_dinv() {
    int i = blockIdx.x * 256 + threadIdx.x;
    if (i < N_NODES) g_dinv[i] = rsqrtf((float)(g_cnt[i] + 1));  // +1 self loop
}

__global__ void k_scan1() {
    __shared__ int sd[256];
    int tid = threadIdx.x;
    int base = blockIdx.x * 1024 + tid * 4;
    int s = 0;
    #pragma unroll
    for (int c = 0; c < 4; ++c)
        if (base + c < N_NODES) s += g_cnt[base + c];
    sd[tid] = s;
    __syncthreads();
    #pragma unroll
    for (int off = 128; off > 0; off >>= 1) {
        if (tid < off) sd[tid] += sd[tid + off];
        __syncthreads();
    }
    if (tid == 0) g_blocksums[blockIdx.x] = sd[0];
}

__global__ void k_scan2() {
    __shared__ int sh[128];
    int tid = threadIdx.x;
    sh[tid] = (tid < NSCAN_BLOCKS) ? g_blocksums[tid] : 0;
    __syncthreads();
    #pragma unroll
    for (int off = 1; off < 128; off <<= 1) {
        int t = (tid >= off) ? sh[tid - off] : 0;
        __syncthreads();
        sh[tid] += t;
        __syncthreads();
    }
    int excl = (tid == 0) ? 0 : sh[tid - 1];
    if (tid < NSCAN_BLOCKS) g_blocksums[tid] = excl;
    if (tid == 0) g_rowptr[N_NODES] = N_EDGES;
}

__global__ void k_scan3() {
    __shared__ int sh[256];
    int tid = threadIdx.x;
    int base = blockIdx.x * 1024 + tid * 4;
    int c0 = 0, c1 = 0, c2 = 0, c3 = 0;
    if (base + 0 < N_NODES) c0 = g_cnt[base + 0];
    if (base + 1 < N_NODES) c1 = g_cnt[base + 1];
    if (base + 2 < N_NODES) c2 = g_cnt[base + 2];
    if (base + 3 < N_NODES) c3 = g_cnt[base + 3];
    sh[tid] = c0 + c1 + c2 + c3;
    __syncthreads();
    #pragma unroll
    for (int off = 1; off < 256; off <<= 1) {
        int t = (tid >= off) ? sh[tid - off] : 0;
        __syncthreads();
        sh[tid] += t;
        __syncthreads();
    }
    int excl = (tid == 0) ? 0 : sh[tid - 1];
    int e = g_blocksums[blockIdx.x] + excl;
    if (base + 0 < N_NODES) { g_rowptr[base + 0] = e;               g_fill[base + 0] = e; }
    if (base + 1 < N_NODES) { g_rowptr[base + 1] = e + c0;           g_fill[base + 1] = e + c0; }
    if (base + 2 < N_NODES) { g_rowptr[base + 2] = e + c0 + c1;      g_fill[base + 2] = e + c0 + c1; }
    if (base + 3 < N_NODES) { g_rowptr[base + 3] = e + c0 + c1 + c2; g_fill[base + 3] = e + c0 + c1 + c2; }
}

__global__ void k_fill(const int* __restrict__ src, const int* __restrict__ dst) {
    int e = blockIdx.x * 256 + threadIdx.x;
    if (e < N_EDGES) {
        int p = atomicAdd(&g_fill[dst[e]], 1);
        g_col[p] = src[e];
    }
}

// ---------------- GEMM: g_hh[i][j] = (half) dinv[i] * sum_k A[i][k] * W[j][k] ----------------
// 128x128 block tile, BK=16, 256 threads, 8x8 per thread, packed f32x2 FMAs.
template <int PHASE>
__global__ __launch_bounds__(256, 2)
void k_gemm(const float* __restrict__ Aext, const float* __restrict__ W, int nrows) {
    const float* __restrict__ A = (PHASE == 0) ? Aext : g_agg;

    __shared__ __align__(16) float As[16][128];
    __shared__ __align__(16) float Bs[16][128];

    const int tid = threadIdx.x;
    const int tx = tid & 15;   // 16 col groups
    const int ty = tid >> 4;   // 16 row groups
    const int rowBase = blockIdx.x * 128;

    u64 c[8][4];
    #pragma unroll
    for (int i = 0; i < 8; ++i)
        #pragma unroll
        for (int j = 0; j < 4; ++j) c[i][j] = 0ull;

    for (int t = 0; t < 8; ++t) {
        const int kk = t * 16;
        __syncthreads();
        #pragma unroll
        for (int it = 0; it < 2; ++it) {
            int f = tid + it * 256;           // 0..511 float4 slots
            int r = f >> 2;
            int kc = (f & 3) * 4;
            int row = rowBase + r;
            float4 v = make_float4(0.f, 0.f, 0.f, 0.f);
            if (row < nrows)
                v = *reinterpret_cast<const float4*>(&A[row * 128 + kk + kc]);
            As[kc + 0][r] = v.x; As[kc + 1][r] = v.y;
            As[kc + 2][r] = v.z; As[kc + 3][r] = v.w;
            float4 w = *reinterpret_cast<const float4*>(&W[r * 128 + kk + kc]);
            Bs[kc + 0][r] = w.x; Bs[kc + 1][r] = w.y;
            Bs[kc + 2][r] = w.z; Bs[kc + 3][r] = w.w;
        }
        __syncthreads();

        #pragma unroll
        for (int k = 0; k < 16; ++k) {
            const float4 a0 = *reinterpret_cast<const float4*>(&As[k][ty * 8]);
            const float4 a1 = *reinterpret_cast<const float4*>(&As[k][ty * 8 + 4]);
            const u64* bp0 = reinterpret_cast<const u64*>(&Bs[k][tx * 4]);
            const u64* bp1 = reinterpret_cast<const u64*>(&Bs[k][64 + tx * 4]);
            u64 b0 = bp0[0], b1 = bp0[1], b2 = bp1[0], b3 = bp1[1];
            float av[8] = {a0.x, a0.y, a0.z, a0.w, a1.x, a1.y, a1.z, a1.w};
            #pragma unroll
            for (int i = 0; i < 8; ++i) {
                u64 aa = pack2dup(av[i]);
                fma2(c[i][0], aa, b0);
                fma2(c[i][1], aa, b1);
                fma2(c[i][2], aa, b2);
                fma2(c[i][3], aa, b3);
            }
        }
    }

    // epilogue: scale by dinv[row], pack to fp16, store 8B per thread per half-row
    #pragma unroll
    for (int i = 0; i < 8; ++i) {
        int row = rowBase + ty * 8 + i;
        if (row < nrows) {
            const float sc = g_dinv[row];
            float2 p0 = unpack2(c[i][0]), p1 = unpack2(c[i][1]);
            __half2 h0 = __floats2half2_rn(p0.x * sc, p0.y * sc);
            __half2 h1 = __floats2half2_rn(p1.x * sc, p1.y * sc);
            uint2 o0;
            o0.x = *reinterpret_cast<u32*>(&h0);
            o0.y = *reinterpret_cast<u32*>(&h1);
            *reinterpret_cast<uint2*>(&g_hh[row * 128 + tx * 4]) = o0;
            float2 p2 = unpack2(c[i][2]), p3 = unpack2(c[i][3]);
            __half2 h2 = __floats2half2_rn(p2.x * sc, p2.y * sc);
            __half2 h3 = __floats2half2_rn(p3.x * sc, p3.y * sc);
            uint2 o1;
            o1.x = *reinterpret_cast<u32*>(&h2);
            o1.y = *reinterpret_cast<u32*>(&h3);
            *reinterpret_cast<uint2*>(&g_hh[row * 128 + 64 + tx * 4]) = o1;
        }
    }
}

// ---------------- Aggregate: out[d] = dinv[d]*(sum_{s in N(d)} hs[s] + hs[d]) + b + perturb
// hs = h pre-scaled by dinv, stored fp16. One warp per node, 4 halfs (8B) per lane.
template <int PHASE>
__global__ __launch_bounds__(256)
void k_agg(const float* __restrict__ bias, const float* __restrict__ perturb,
           float* __restrict__ outParam) {
    int gw = (blockIdx.x * 256 + threadIdx.x) >> 5;
    if (gw >= N_NODES) return;
    const int lane = threadIdx.x & 31;
    const uint2* __restrict__ hv = reinterpret_cast<const uint2*>(g_hh);
    float* __restrict__ outp = (PHASE == 0) ? g_agg : outParam;

    const int d = gw;
    const float dd = g_dinv[d];

    uint2 u = hv[d * 32 + lane];              // self loop (already scaled by dinv[d])
    float2 f0 = __half22float2(*reinterpret_cast<__half2*>(&u.x));
    float2 f1 = __half22float2(*reinterpret_cast<__half2*>(&u.y));
    float ax = f0.x, ay = f0.y, az = f1.x, aw = f1.y;

    int j = g_rowptr[d];
    const int end = g_rowptr[d + 1];
    for (; j + 4 <= end; j += 4) {
        int s0 = g_col[j + 0], s1 = g_col[j + 1], s2 = g_col[j + 2], s3 = g_col[j + 3];
        uint2 u0 = hv[s0 * 32 + lane];
        uint2 u1 = hv[s1 * 32 + lane];
        uint2 u2 = hv[s2 * 32 + lane];
        uint2 u3 = hv[s3 * 32 + lane];
        float2 a0 = __half22float2(*reinterpret_cast<__half2*>(&u0.x));
        float2 b0 = __half22float2(*reinterpret_cast<__half2*>(&u0.y));
        float2 a1 = __half22float2(*reinterpret_cast<__half2*>(&u1.x));
        float2 b1 = __half22float2(*reinterpret_cast<__half2*>(&u1.y));
        float2 a2 = __half22float2(*reinterpret_cast<__half2*>(&u2.x));
        float2 b2 = __half22float2(*reinterpret_cast<__half2*>(&u2.y));
        float2 a3 = __half22float2(*reinterpret_cast<__half2*>(&u3.x));
        float2 b3 = __half22float2(*reinterpret_cast<__half2*>(&u3.y));
        ax += a0.x + a1.x + a2.x + a3.x;
        ay += a0.y + a1.y + a2.y + a3.y;
        az += b0.x + b1.x + b2.x + b3.x;
        aw += b0.y + b1.y + b2.y + b3.y;
    }
    for (; j < end; ++j) {
        int s = g_col[j];
        uint2 uu = hv[s * 32 + lane];
        float2 aa = __half22float2(*reinterpret_cast<__half2*>(&uu.x));
        float2 bb = __half22float2(*reinterpret_cast<__half2*>(&uu.y));
        ax += aa.x; ay += aa.y; az += bb.x; aw += bb.y;
    }

    float4 b = reinterpret_cast<const float4*>(bias)[lane];
    float4 p = reinterpret_cast<const float4*>(perturb)[d * 32 + lane];
    float4 o;
    o.x = ax * dd + b.x + p.x;
    o.y = ay * dd + b.y + p.y;
    o.z = az * dd + b.z + p.z;
    o.w = aw * dd + b.w + p.w;
    reinterpret_cast<float4*>(outp)[d * 32 + lane] = o;
}

// ---------------- launch ----------------
extern "C" void kernel_launch(void* const* d_in, const int* in_sizes, int n_in,
                              void* d_out, int out_size) {
    const float* x  = (const float*)d_in[0];
    const int*   ei = (const int*)d_in[1];
    const float* pf = (const float*)d_in[2];
    const float* pl = (const float*)d_in[3];
    const float* W1 = (const float*)d_in[4];
    const float* b1 = (const float*)d_in[5];
    const float* W2 = (const float*)d_in[6];
    const float* b2 = (const float*)d_in[7];
    float* out = (float*)d_out;
    const int* src = ei;
    const int* dst = ei + N_EDGES;

    const int nb_nodes = (N_NODES + 255) / 256;       // 391
    const int nb_edges = (N_EDGES + 255) / 256;       // 6250
    const int nb_gemm  = (N_NODES + 127) / 128;       // 782
    const int nb_agg   = (N_NODES + 7) / 8;           // 12500

    // CSR + norm build (per call; deterministic work)
    k_zero<<<nb_nodes, 256>>>();
    k_hist<<<nb_edges, 256>>>(dst);
    k_dinv<<<nb_nodes, 256>>>();
    k_scan1<<<NSCAN_BLOCKS, 256>>>();
    k_scan2<<<1, 128>>>();
    k_scan3<<<NSCAN_BLOCKS, 256>>>();
    k_fill<<<nb_edges, 256>>>(src, dst);

    // layer 1
    k_gemm<0><<<nb_gemm, 256>>>(x, W1, N_NODES);
    k_agg<0><<<nb_agg, 256>>>(b1, pf, nullptr);
    // layer 2
    k_gemm<1><<<nb_gemm, 256>>>(nullptr, W2, N_NODES);
    k_agg<1><<<nb_agg, 256>>>(b2, pl, out);
}